// round 1
// baseline (speedup 1.0000x reference)
#include <cuda_runtime.h>
#include <cuda_bf16.h>
#include <math.h>

#define NPATCH 8192
#define KC     10
#define DIN    1024
#define DH     512
#define DA     256
#define NCLS   4

// ---------------- device scratch (no allocations allowed) ----------------
__device__ int   g_cnt[KC];
__device__ int   g_off[KC + 1];
__device__ int   g_cursor[KC];
__device__ int   g_order[NPATCH];
__device__ float g_H1[(size_t)NPATCH * DH];     // 16 MB
__device__ float g_psum[KC * DH];

// ---------------- small setup kernels ----------------
__global__ void k_init() {
    int tid = blockIdx.x * blockDim.x + threadIdx.x;
    if (tid < KC) { g_cnt[tid] = 0; g_cursor[tid] = 0; }
    for (int i = tid; i < KC * DH; i += gridDim.x * blockDim.x) g_psum[i] = 0.f;
}

__global__ void k_hist(const int* __restrict__ cid, int n) {
    int i = blockIdx.x * blockDim.x + threadIdx.x;
    if (i < n) atomicAdd(&g_cnt[cid[i]], 1);
}

__global__ void k_offsets() {
    int s = 0;
    g_off[0] = 0;
    for (int k = 0; k < KC; k++) { s += g_cnt[k]; g_off[k + 1] = s; }
}

__global__ void k_scatter(const int* __restrict__ cid, int n) {
    int i = blockIdx.x * blockDim.x + threadIdx.x;
    if (i < n) {
        int c = cid[i];
        int pos = g_off[c] + atomicAdd(&g_cursor[c], 1);
        g_order[pos] = i;
    }
}

// ---------------- GEMM1: H1[r,:] = relu(x[order[r],:] @ W1[k] + b1[k]) ----------------
// 128x128 tile, BK=8, 256 threads, 8x8 per-thread microtile
__global__ __launch_bounds__(256) void k_gemm1(const float* __restrict__ x,
                                               const float* __restrict__ W1,
                                               const float* __restrict__ b1) {
    int k = blockIdx.z;
    int row0 = g_off[k] + blockIdx.y * 128;
    int rend = g_off[k + 1];
    if (row0 >= rend) return;
    int col0 = blockIdx.x * 128;

    __shared__ float smem[2048];
    float* As = smem;          // [8][128], As[kk][row]
    float* Bs = smem + 1024;   // [8][128], Bs[kk][col]

    int tid = threadIdx.x;
    int tx = tid & 15, ty = tid >> 4;

    float acc[8][8];
#pragma unroll
    for (int i = 0; i < 8; i++)
#pragma unroll
        for (int j = 0; j < 8; j++) acc[i][j] = 0.f;

    int arow = tid >> 1;
    int ak4  = (tid & 1) * 4;
    int grow = row0 + arow;
    bool rvalid = grow < rend;
    const float* xrow = x + (rvalid ? (size_t)g_order[grow] * DIN : 0);

    int bk   = tid >> 5;
    int bcol = (tid & 31) * 4;
    const float* Wb = W1 + (size_t)k * DIN * DH + (size_t)bk * DH + col0 + bcol;

    for (int kk0 = 0; kk0 < DIN; kk0 += 8) {
        float4 av = rvalid ? *(const float4*)(xrow + kk0 + ak4) : make_float4(0.f, 0.f, 0.f, 0.f);
        As[(ak4 + 0) * 128 + arow] = av.x;
        As[(ak4 + 1) * 128 + arow] = av.y;
        As[(ak4 + 2) * 128 + arow] = av.z;
        As[(ak4 + 3) * 128 + arow] = av.w;
        *(float4*)&Bs[bk * 128 + bcol] = *(const float4*)(Wb + (size_t)kk0 * DH);
        __syncthreads();
#pragma unroll
        for (int kk = 0; kk < 8; kk++) {
            float a[8], b[8];
#pragma unroll
            for (int i = 0; i < 8; i++) a[i] = As[kk * 128 + ty * 8 + i];
#pragma unroll
            for (int j = 0; j < 8; j++) b[j] = Bs[kk * 128 + tx * 8 + j];
#pragma unroll
            for (int i = 0; i < 8; i++)
#pragma unroll
                for (int j = 0; j < 8; j++) acc[i][j] += a[i] * b[j];
        }
        __syncthreads();
    }

#pragma unroll
    for (int i = 0; i < 8; i++) {
        int r = row0 + ty * 8 + i;
        if (r < rend) {
            float* dst = g_H1 + (size_t)r * DH + col0 + tx * 8;
#pragma unroll
            for (int j = 0; j < 8; j++) {
                float v = acc[i][j] + b1[k * DH + col0 + tx * 8 + j];
                dst[j] = fmaxf(v, 0.f);
            }
        }
    }
}

// ---------------- GEMM2: psum[k,:] += colsum( relu(H1 @ W2[k] + b2[k]) ) ----------------
__global__ __launch_bounds__(256) void k_gemm2(const float* __restrict__ W2,
                                               const float* __restrict__ b2) {
    int k = blockIdx.z;
    int row0 = g_off[k] + blockIdx.y * 128;
    int rend = g_off[k + 1];
    if (row0 >= rend) return;
    int col0 = blockIdx.x * 128;

    __shared__ float smem[2048];
    float* As = smem;
    float* Bs = smem + 1024;

    int tid = threadIdx.x;
    int tx = tid & 15, ty = tid >> 4;

    float acc[8][8];
#pragma unroll
    for (int i = 0; i < 8; i++)
#pragma unroll
        for (int j = 0; j < 8; j++) acc[i][j] = 0.f;

    int arow = tid >> 1;
    int ak4  = (tid & 1) * 4;
    int grow = row0 + arow;
    bool rvalid = grow < rend;
    const float* hrow = g_H1 + (rvalid ? (size_t)grow * DH : 0);

    int bk   = tid >> 5;
    int bcol = (tid & 31) * 4;
    const float* Wb = W2 + (size_t)k * DH * DH + (size_t)bk * DH + col0 + bcol;

    for (int kk0 = 0; kk0 < DH; kk0 += 8) {
        float4 av = rvalid ? *(const float4*)(hrow + kk0 + ak4) : make_float4(0.f, 0.f, 0.f, 0.f);
        As[(ak4 + 0) * 128 + arow] = av.x;
        As[(ak4 + 1) * 128 + arow] = av.y;
        As[(ak4 + 2) * 128 + arow] = av.z;
        As[(ak4 + 3) * 128 + arow] = av.w;
        *(float4*)&Bs[bk * 128 + bcol] = *(const float4*)(Wb + (size_t)kk0 * DH);
        __syncthreads();
#pragma unroll
        for (int kk = 0; kk < 8; kk++) {
            float a[8], b[8];
#pragma unroll
            for (int i = 0; i < 8; i++) a[i] = As[kk * 128 + ty * 8 + i];
#pragma unroll
            for (int j = 0; j < 8; j++) b[j] = Bs[kk * 128 + tx * 8 + j];
#pragma unroll
            for (int i = 0; i < 8; i++)
#pragma unroll
                for (int j = 0; j < 8; j++) acc[i][j] += a[i] * b[j];
        }
        __syncthreads();
    }

    // relu(+bias) and per-thread row sums
    float csum[8];
#pragma unroll
    for (int j = 0; j < 8; j++) csum[j] = 0.f;
#pragma unroll
    for (int i = 0; i < 8; i++) {
        int r = row0 + ty * 8 + i;
        if (r < rend) {
#pragma unroll
            for (int j = 0; j < 8; j++) {
                float v = acc[i][j] + b2[k * DH + col0 + tx * 8 + j];
                csum[j] += fmaxf(v, 0.f);
            }
        }
    }
    // block reduce over ty (16) per column (128 cols) reusing smem
    __syncthreads();
#pragma unroll
    for (int j = 0; j < 8; j++) smem[ty * 128 + tx * 8 + j] = csum[j];
    __syncthreads();
    if (tid < 128) {
        float s = 0.f;
#pragma unroll
        for (int t = 0; t < 16; t++) s += smem[t * 128 + tid];
        atomicAdd(&g_psum[k * DH + col0 + tid], s);
    }
}

// ---------------- head: pooling -> fc -> gated attention -> rho -> classifier ----------------
__global__ __launch_bounds__(512) void k_head(const float* __restrict__ fc_W, const float* __restrict__ fc_b,
                                              const float* __restrict__ Va,   const float* __restrict__ ba,
                                              const float* __restrict__ Vb,   const float* __restrict__ bb,
                                              const float* __restrict__ Vc,   const float* __restrict__ bc,
                                              const float* __restrict__ rho_W, const float* __restrict__ rho_b,
                                              const float* __restrict__ cls_W, const float* __restrict__ cls_b,
                                              float* __restrict__ out, int out_size) {
    __shared__ float pooled_s[KC * DH];   // 20 KB
    __shared__ float h_s[KC * DH];        // 20 KB
    __shared__ float hpath[DH];
    __shared__ float hp2[DA];
    __shared__ float Alog[KC];
    __shared__ float attw[KC];
    __shared__ float logits_s[NCLS];

    int tid = threadIdx.x;

    // Stage A: pooled = psum / max(cnt,1), zero if empty
    for (int idx = tid; idx < KC * DH; idx += 512) {
        int k = idx / DH;
        int c = g_cnt[k];
        pooled_s[idx] = (c > 0) ? g_psum[idx] / (float)c : 0.f;
    }
    if (tid < KC) Alog[tid] = bc[0];
    if (tid < NCLS) logits_s[tid] = cls_b[tid];
    __syncthreads();

    // Stage B: h[k][j] = relu(pooled[k] @ fc_W + fc_b)   (thread = column j)
    {
        int j = tid;
        float acc[KC];
#pragma unroll
        for (int k = 0; k < KC; k++) acc[k] = fc_b[j];
        for (int i = 0; i < DH; i++) {
            float w = fc_W[i * DH + j];
#pragma unroll
            for (int k = 0; k < KC; k++) acc[k] += pooled_s[k * DH + i] * w;
        }
#pragma unroll
        for (int k = 0; k < KC; k++) h_s[k * DH + j] = fmaxf(acc[k], 0.f);
    }
    __syncthreads();

    // Stage C: gated attention logits A[k] = sum_m tanh(h@Va+ba)*sigmoid(h@Vb+bb)*Vc[m] + bc
    if (tid < DA) {
        int m = tid;
        float aA[KC], aB[KC];
#pragma unroll
        for (int k = 0; k < KC; k++) { aA[k] = ba[m]; aB[k] = bb[m]; }
        for (int j = 0; j < DH; j++) {
            float va = Va[j * DA + m];
            float vb = Vb[j * DA + m];
#pragma unroll
            for (int k = 0; k < KC; k++) {
                float hv = h_s[k * DH + j];
                aA[k] += hv * va;
                aB[k] += hv * vb;
            }
        }
        float vc = Vc[m];
#pragma unroll
        for (int k = 0; k < KC; k++) {
            float contrib = tanhf(aA[k]) * (1.f / (1.f + expf(-aB[k]))) * vc;
            atomicAdd(&Alog[k], contrib);
        }
    }
    __syncthreads();

    // Stage D: softmax over K (thread 0)
    if (tid == 0) {
        float mx = -1e30f;
        for (int k = 0; k < KC; k++) mx = fmaxf(mx, Alog[k]);
        float s = 0.f;
        for (int k = 0; k < KC; k++) { float e = expf(Alog[k] - mx); attw[k] = e; s += e; }
        float inv = 1.f / s;
        for (int k = 0; k < KC; k++) attw[k] *= inv;
    }
    __syncthreads();

    // Stage E: h_path[j] = sum_k attw[k]*h[k][j]
    {
        int j = tid;
        float s = 0.f;
#pragma unroll
        for (int k = 0; k < KC; k++) s += attw[k] * h_s[k * DH + j];
        hpath[j] = s;
    }
    __syncthreads();

    // Stage F: hp2 = relu(h_path @ rho_W + rho_b)
    if (tid < DA) {
        int m = tid;
        float acc = rho_b[m];
        for (int j = 0; j < DH; j++) acc += hpath[j] * rho_W[j * DA + m];
        hp2[m] = fmaxf(acc, 0.f);
    }
    __syncthreads();

    // Stage G: logits = hp2 @ cls_W + cls_b
    if (tid < DA) {
        int m = tid;
        float v = hp2[m];
#pragma unroll
        for (int c = 0; c < NCLS; c++) atomicAdd(&logits_s[c], v * cls_W[m * NCLS + c]);
    }
    __syncthreads();

    // Stage H: hazards, S cumprod, argmax; write output
    if (tid == 0) {
        float haz[NCLS], S[NCLS];
        float run = 1.f;
        int best = 0;
        float bval = logits_s[0];
        for (int c = 0; c < NCLS; c++) {
            if (logits_s[c] > bval) { bval = logits_s[c]; best = c; }
            haz[c] = 1.f / (1.f + expf(-logits_s[c]));
            run *= (1.f - haz[c]);
            S[c] = run;
        }
        float vals[9];
        for (int c = 0; c < NCLS; c++) vals[c] = haz[c];
        for (int c = 0; c < NCLS; c++) vals[NCLS + c] = S[c];
        vals[8] = (float)best;
        for (int i = 0; i < out_size; i++) out[i] = (i < 9) ? vals[i] : 0.f;
    }
}

// ---------------- launch ----------------
extern "C" void kernel_launch(void* const* d_in, const int* in_sizes, int n_in,
                              void* d_out, int out_size) {
    const float* x     = (const float*)d_in[0];
    const int*   cid   = (const int*)d_in[1];
    const float* W1    = (const float*)d_in[2];
    const float* b1    = (const float*)d_in[3];
    const float* W2    = (const float*)d_in[4];
    const float* b2    = (const float*)d_in[5];
    const float* fc_W  = (const float*)d_in[6];
    const float* fc_b  = (const float*)d_in[7];
    const float* Va    = (const float*)d_in[8];
    const float* ba    = (const float*)d_in[9];
    const float* Vb    = (const float*)d_in[10];
    const float* bb    = (const float*)d_in[11];
    const float* Vc    = (const float*)d_in[12];
    const float* bc    = (const float*)d_in[13];
    const float* rho_W = (const float*)d_in[14];
    const float* rho_b = (const float*)d_in[15];
    const float* cls_W = (const float*)d_in[16];
    const float* cls_b = (const float*)d_in[17];
    float* out = (float*)d_out;

    int n = in_sizes[0] / DIN;   // 8192

    k_init<<<32, 256>>>();
    k_hist<<<(n + 255) / 256, 256>>>(cid, n);
    k_offsets<<<1, 1>>>();
    k_scatter<<<(n + 255) / 256, 256>>>(cid, n);

    dim3 grid(DH / 128, (n + 127) / 128, KC);
    k_gemm1<<<grid, 256>>>(x, W1, b1);
    k_gemm2<<<grid, 256>>>(W2, b2);

    k_head<<<1, 512>>>(fc_W, fc_b, Va, ba, Vb, bb, Vc, bc,
                       rho_W, rho_b, cls_W, cls_b, out, out_size);
}